// round 1
// baseline (speedup 1.0000x reference)
#include <cuda_runtime.h>
#include <math.h>

#define PP 2
#define BB 96
#define AA 32
#define NATOM (BB*AA)        // 3072
#define NPOLB 8
#define NPOL (BB*NPOLB)      // 768
#define MD 4
#define MA 4
#define C_LK 0.0897935610625833f
#define JSPLIT 4

// ---------------- device scratch (no allocation allowed) ----------------
__device__ float4   g_jpos[PP*NATOM];   // x,y,z, rj   (per pose-atom)
__device__ float    g_jvol[PP*NATOM];   // volj (0 if hydrogen)
__device__ float4   g_polA[PP*NPOL];    // xp.x, xp.y, xp.z, (unused)   sentinel 1e9 if invalid
__device__ float4   g_polB[PP*NPOL];    // Ki = C*dgi/lami, inv_lami, ri, intraMask(bits)
__device__ float4   g_w0[PP*NPOL];      // water0 xyz (sentinel 1e4 if invalid)
__device__ float4   g_w1[PP*NPOL];      // water1 xyz
__device__ unsigned g_bp[PP*BB*3];      // per (p, b_i): 96-bit inter-block sep>=4 mask

struct F3 { float x, y, z; };
__device__ __forceinline__ F3 ld3(const float* p){ F3 r; r.x=p[0]; r.y=p[1]; r.z=p[2]; return r; }
__device__ __forceinline__ F3 sub3(F3 a, F3 b){ F3 r; r.x=a.x-b.x; r.y=a.y-b.y; r.z=a.z-b.z; return r; }
__device__ __forceinline__ float dot3(F3 a, F3 b){ return a.x*b.x + a.y*b.y + a.z*b.z; }
__device__ __forceinline__ F3 cross3(F3 a, F3 b){
    F3 r; r.x = a.y*b.z - a.z*b.y; r.y = a.z*b.x - a.x*b.z; r.z = a.x*b.y - a.y*b.x; return r;
}
__device__ __forceinline__ F3 norm3(F3 a){
    float inv = rsqrtf(dot3(a,a) + 1e-12f);
    F3 r; r.x=a.x*inv; r.y=a.y*inv; r.z=a.z*inv; return r;
}

// ---------------- prep: waters, polar data, j-data, masks, zero out ----------------
__global__ void prep_kernel(
    const float* __restrict__ coords,       // (P, N, 3)
    const int*   __restrict__ btype,        // (P, B)
    const int*   __restrict__ msep,         // (P, B, B)
    const int*   __restrict__ bonds,        // (NT, A, 2)
    const int*   __restrict__ ranges,       // (NT, A, 2)
    const int*   __restrict__ n_donH,       // (NT,)
    const int*   __restrict__ n_acc,        // (NT,)
    const int*   __restrict__ donH,         // (NT, MD)
    const int*   __restrict__ donHvy,       // (NT, MD)
    const int*   __restrict__ accI,         // (NT, MA)
    const int*   __restrict__ hyb,          // (NT, MA)
    const int*   __restrict__ isH,          // (NT, A)
    const float* __restrict__ lkp,          // (NT, A, 4)
    const int*   __restrict__ pd,           // (NT, A, A)
    const float* __restrict__ wgp,          // (2,)
    const float* __restrict__ sp2t,         // (2,)
    const float* __restrict__ sp3t,         // (2,)
    const float* __restrict__ ringt,        // (2,)
    float* __restrict__ out)
{
    int t = blockIdx.x * blockDim.x + threadIdx.x;

    if (t < 2*PP) out[t] = 0.0f;

    // ---- per-atom j data ----
    if (t < PP*NATOM) {
        int p = t / NATOM, j = t % NATOM;
        int b = j >> 5, a = j & 31;
        int bt = btype[p*BB + b];
        const float* pr = lkp + (bt*AA + a)*4;
        const float* c  = coords + t*3;
        float4 q; q.x = c[0]; q.y = c[1]; q.z = c[2]; q.w = pr[0];
        g_jpos[t] = q;
        g_jvol[t] = (isH[bt*AA + a] == 0) ? pr[3] : 0.0f;
    }

    // ---- per (p, b_i) inter-block separation bitmask ----
    if (t < PP*BB*3) {
        int w = t % 3; int pb = t / 3;
        const int* row = msep + pb*BB;
        unsigned bits = 0u;
        #pragma unroll
        for (int k = 0; k < 32; k++) {
            int bj = w*32 + k;
            if (row[bj] >= 4) bits |= (1u << k);
        }
        g_bp[t] = bits;
    }

    // ---- per polar slot: waters + params ----
    if (t < PP*BB*NPOLB) {
        int p = t / (BB*NPOLB);
        int r = t % (BB*NPOLB);
        int b = r / NPOLB;
        int k = r % NPOLB;
        int bt = btype[p*BB + b];
        const float* cb = coords + (p*NATOM + b*AA)*3;
        float wdist = wgp[0], wang = wgp[1];

        F3 w0v, w1v;
        int pol;
        bool valid;

        if (k < MD) {
            int hv = donHvy[bt*MD + k];
            int hh = donH  [bt*MD + k];
            valid = (k < n_donH[bt]);
            pol = hv;
            F3 Pv = ld3(cb + hv*3);
            F3 Hh = ld3(cb + hh*3);
            F3 dv = sub3(Hh, Pv);
            float inv = rsqrtf(dot3(dv,dv) + 1e-12f);
            float s = wdist * inv;
            w0v.x = Pv.x + s*dv.x; w0v.y = Pv.y + s*dv.y; w0v.z = Pv.z + s*dv.z;
            w1v.x = 1e4f; w1v.y = 1e4f; w1v.z = 1e4f;      // donor water1 invalid
        } else {
            int m = k - MD;
            int a = accI[bt*MA + m];
            valid = (m < n_acc[bt]);
            pol = a;
            int rr    = ranges[(bt*AA + a)*2];
            int base  = bonds [(bt*AA + rr)*2 + 1];
            int rr2   = ranges[(bt*AA + base)*2];
            int base2 = bonds [(bt*AA + rr2)*2 + 1];
            F3 c  = ld3(cb + a*3);
            F3 bz = ld3(cb + base*3);
            F3 az = ld3(cb + base2*3);
            F3 e1 = norm3(sub3(c, bz));
            F3 nv = norm3(cross3(sub3(bz, az), e1));
            F3 e2 = cross3(nv, e1);
            int hy = hyb[bt*MA + m];
            const float* tors = (hy == 0) ? sp2t : ((hy == 1) ? sp3t : ringt);
            float ct = cosf(wang), st = sinf(wang);
            float c1 = -wdist * ct;
            {
                float c2 = wdist * st * cosf(tors[0]);
                float c3 = wdist * st * sinf(tors[0]);
                w0v.x = c.x + c1*e1.x + c2*e2.x + c3*nv.x;
                w0v.y = c.y + c1*e1.y + c2*e2.y + c3*nv.y;
                w0v.z = c.z + c1*e1.z + c2*e2.z + c3*nv.z;
            }
            {
                float c2 = wdist * st * cosf(tors[1]);
                float c3 = wdist * st * sinf(tors[1]);
                w1v.x = c.x + c1*e1.x + c2*e2.x + c3*nv.x;
                w1v.y = c.y + c1*e1.y + c2*e2.y + c3*nv.y;
                w1v.z = c.z + c1*e1.z + c2*e2.z + c3*nv.z;
            }
        }

        const float* pr = lkp + (bt*AA + pol)*4;
        float ri = pr[0], dgi = pr[1], lami = pr[2];

        float4 pa;
        if (valid) {
            const float* xc = cb + pol*3;
            pa.x = xc[0]; pa.y = xc[1]; pa.z = xc[2];
        } else {
            pa.x = 1e9f; pa.y = 1e9f; pa.z = 1e9f;   // sentinel: never inside cutoff
        }
        pa.w = 0.0f;
        g_polA[t] = pa;

        unsigned im = 0u;
        const int* pdr = pd + (bt*AA + pol)*AA;
        #pragma unroll
        for (int aj = 0; aj < AA; aj++)
            if (pdr[aj] >= 4) im |= (1u << aj);

        float4 pb4;
        pb4.x = C_LK * dgi / lami;
        pb4.y = 1.0f / lami;
        pb4.z = ri;
        pb4.w = __uint_as_float(im);
        g_polB[t] = pb4;

        float4 w0q; w0q.x = w0v.x; w0q.y = w0v.y; w0q.z = w0v.z; w0q.w = 0.f;
        float4 w1q; w1q.x = w1v.x; w1q.y = w1v.y; w1q.z = w1v.z; w1q.w = 0.f;
        g_w0[t] = w0q;
        g_w1[t] = w1q;
    }
}

// ---------------- main pairwise kernel ----------------
__global__ __launch_bounds__(256, 4)
void pair_kernel(const float* __restrict__ lkg, float* __restrict__ out)
{
    const int p   = blockIdx.x / BB;
    const int b   = blockIdx.x % BB;
    const int tid = threadIdx.x;

    __shared__ float sW[NPOLB][8];    // per i: w0.xyz, w1.xyz, (2 pad)
    __shared__ float sM[NPOLB][4];    // per i: Ki, inv_lami, ri
    __shared__ float sred[2][8];

    const int ibase = p*NPOL + b*NPOLB;

    if (tid < NPOLB) {
        float4 w0 = g_w0[ibase + tid];
        float4 w1 = g_w1[ibase + tid];
        sW[tid][0] = w0.x; sW[tid][1] = w0.y; sW[tid][2] = w0.z;
        sW[tid][3] = w1.x; sW[tid][4] = w1.y; sW[tid][5] = w1.z;
        float4 pb4 = g_polB[ibase + tid];
        sM[tid][0] = pb4.x; sM[tid][1] = pb4.y; sM[tid][2] = pb4.z;
    }

    // loop-invariant per-site data in registers
    float xpx[NPOLB], xpy[NPOLB], xpz[NPOLB];
    unsigned im[NPOLB];
    #pragma unroll
    for (int i = 0; i < NPOLB; i++) {
        float4 a4 = g_polA[ibase + i];
        xpx[i] = a4.x; xpy[i] = a4.y; xpz[i] = a4.z;
        float4 b4 = g_polB[ibase + i];
        im[i] = __float_as_uint(b4.w);
    }
    const unsigned bp0 = g_bp[(p*BB + b)*3 + 0];
    const unsigned bp1 = g_bp[(p*BB + b)*3 + 1];
    const unsigned bp2 = g_bp[(p*BB + b)*3 + 2];

    const float cutoff = lkg[0];
    const float cut2   = cutoff * cutoff;
    const float ramp2  = lkg[1];
    const float c0     = lkg[2] + ramp2;     // d2_low + ramp2
    const float invr   = 1.0f / ramp2;

    __syncthreads();

    float s0 = 0.0f, s1 = 0.0f;

    const int chunk = NATOM / JSPLIT;        // 768
    const int j0 = blockIdx.y * chunk;
    const int pbase = p * NATOM;

    for (int jj = tid; jj < chunk; jj += 256) {
        int j = j0 + jj;
        float4 cj = g_jpos[pbase + j];
        float vj  = g_jvol[pbase + j];
        int bj = j >> 5;
        int aj = j & 31;
        unsigned interbit =
            ((bj < 32) ? (bp0 >> bj) : (bj < 64) ? (bp1 >> (bj - 32)) : (bp2 >> (bj - 64))) & 1u;
        bool same = (bj == b);

        #pragma unroll
        for (int i = 0; i < NPOLB; i++) {
            unsigned sep = same ? ((im[i] >> aj) & 1u) : interbit;
            float dx = xpx[i] - cj.x;
            float dy = xpy[i] - cj.y;
            float dz = xpz[i] - cj.z;
            float d2 = fmaf(dx, dx, fmaf(dy, dy, dz*dz));
            if (sep && (d2 < cut2) && (vj > 0.0f)) {
                d2 = fmaxf(d2, 0.01f);
                float d  = sqrtf(d2);
                float Ki = sM[i][0];
                float il = sM[i][1];
                float ri = sM[i][2];
                float x  = (d - ri - cj.w) * il;
                float lk = __fdividef(Ki * vj * __expf(-x*x), d2);
                float ax = sW[i][0] - cj.x, ay = sW[i][1] - cj.y, az = sW[i][2] - cj.z;
                float d2a = fmaf(ax, ax, fmaf(ay, ay, az*az));
                float bx = sW[i][3] - cj.x, by = sW[i][4] - cj.y, bz = sW[i][5] - cj.z;
                float d2b = fmaf(bx, bx, fmaf(by, by, bz*bz));
                float dm = fminf(d2a, d2b);
                float wt = __saturatef((c0 - dm) * invr);
                float frac = wt * wt * (3.0f - 2.0f*wt);
                s0 += lk;
                s1 += lk * frac;
            }
        }
    }

    // reduction: warp shuffle then cross-warp via shared
    #pragma unroll
    for (int off = 16; off > 0; off >>= 1) {
        s0 += __shfl_xor_sync(0xFFFFFFFFu, s0, off);
        s1 += __shfl_xor_sync(0xFFFFFFFFu, s1, off);
    }
    int wid  = tid >> 5;
    int lane = tid & 31;
    if (lane == 0) { sred[0][wid] = s0; sred[1][wid] = s1; }
    __syncthreads();
    if (tid == 0) {
        float t0 = 0.f, t1 = 0.f;
        #pragma unroll
        for (int w = 0; w < 8; w++) { t0 += sred[0][w]; t1 += sred[1][w]; }
        atomicAdd(&out[p],      t0);   // row 0 of (2, P)
        atomicAdd(&out[PP + p], t1);   // row 1 of (2, P)
    }
}

// ---------------- launch ----------------
extern "C" void kernel_launch(void* const* d_in, const int* in_sizes, int n_in,
                              void* d_out, int out_size)
{
    const float* coords = (const float*)d_in[0];
    const int*   btype  = (const int*)  d_in[1];
    const int*   msep   = (const int*)  d_in[2];
    /* d_in[3] = bt_n_atoms (unused, always A) */
    const int*   bonds  = (const int*)  d_in[4];
    const int*   ranges = (const int*)  d_in[5];
    const int*   ndonH  = (const int*)  d_in[6];
    const int*   nacc   = (const int*)  d_in[7];
    const int*   donH   = (const int*)  d_in[8];
    const int*   donHvy = (const int*)  d_in[9];
    const int*   accI   = (const int*)  d_in[10];
    const int*   hyb    = (const int*)  d_in[11];
    const int*   isH    = (const int*)  d_in[12];
    const float* lkp    = (const float*)d_in[13];
    const int*   pd     = (const int*)  d_in[14];
    const float* lkg    = (const float*)d_in[15];
    const float* wgp    = (const float*)d_in[16];
    const float* sp2t   = (const float*)d_in[17];
    const float* sp3t   = (const float*)d_in[18];
    const float* ringt  = (const float*)d_in[19];
    float* out = (float*)d_out;

    prep_kernel<<<24, 256>>>(coords, btype, msep, bonds, ranges, ndonH, nacc,
                             donH, donHvy, accI, hyb, isH, lkp, pd,
                             wgp, sp2t, sp3t, ringt, out);

    dim3 grid(PP*BB, JSPLIT);
    pair_kernel<<<grid, 256>>>(lkg, out);
}

// round 2
// speedup vs baseline: 1.3634x; 1.3634x over previous
#include <cuda_runtime.h>
#include <math.h>

#define PP 2
#define BB 96
#define AA 32
#define NATOM (BB*AA)        // 3072
#define NPOLB 8
#define MD 4
#define MA 4
#define C_LK 0.0897935610625833f
#define JSPLIT 4
#define CHUNK (NATOM/JSPLIT) // 768
#define NBLK (PP*BB*JSPLIT)  // 768

// persistent accumulators (zero-initialized at module load; self-resetting each launch)
__device__ float    g_acc[4];
__device__ unsigned g_cnt;

struct F3 { float x, y, z; };
__device__ __forceinline__ F3 ld3(const float* p){ F3 r; r.x=p[0]; r.y=p[1]; r.z=p[2]; return r; }
__device__ __forceinline__ F3 sub3(F3 a, F3 b){ F3 r; r.x=a.x-b.x; r.y=a.y-b.y; r.z=a.z-b.z; return r; }
__device__ __forceinline__ float dot3(F3 a, F3 b){ return a.x*b.x + a.y*b.y + a.z*b.z; }
__device__ __forceinline__ F3 cross3(F3 a, F3 b){
    F3 r; r.x = a.y*b.z - a.z*b.y; r.y = a.z*b.x - a.x*b.z; r.z = a.x*b.y - a.y*b.x; return r;
}
__device__ __forceinline__ F3 norm3(F3 a){
    float inv = rsqrtf(dot3(a,a) + 1e-12f);
    F3 r; r.x=a.x*inv; r.y=a.y*inv; r.z=a.z*inv; return r;
}

__global__ __launch_bounds__(256, 5)
void lkball_fused_kernel(
    const float* __restrict__ coords,       // (P, N, 3)
    const int*   __restrict__ btype,        // (P, B)
    const int*   __restrict__ msep,         // (P, B, B)
    const int*   __restrict__ bonds,        // (NT, A, 2)
    const int*   __restrict__ ranges,       // (NT, A, 2)
    const int*   __restrict__ n_donH,       // (NT,)
    const int*   __restrict__ n_acc,        // (NT,)
    const int*   __restrict__ donH,         // (NT, MD)
    const int*   __restrict__ donHvy,       // (NT, MD)
    const int*   __restrict__ accI,         // (NT, MA)
    const int*   __restrict__ hyb,          // (NT, MA)
    const int*   __restrict__ isH,          // (NT, A)
    const float* __restrict__ lkp,          // (NT, A, 4)
    const int*   __restrict__ pd,           // (NT, A, A)
    const float* __restrict__ lkg,          // (3,)
    const float* __restrict__ wgp,          // (2,)
    const float* __restrict__ sp2t,         // (2,)
    const float* __restrict__ sp3t,         // (2,)
    const float* __restrict__ ringt,        // (2,)
    float* __restrict__ out)
{
    const int p   = blockIdx.x / BB;
    const int b   = blockIdx.x % BB;
    const int tid = threadIdx.x;

    // per-site: [0..2]=xp, [3]=Ki, [4]=inv_lami, [5]=ri, [6..8]=w0, [9..11]=w1
    __shared__ float         sSite[NPOLB][12];
    __shared__ int           sPol[NPOLB];
    __shared__ unsigned      sIm[NPOLB];
    __shared__ unsigned char sSame[AA];     // per aj: 8-bit site mask (intra sep>=4)
    __shared__ unsigned      sBp[3];        // 96-bit inter-block sep>=4 mask
    __shared__ float         sred[2][8];

    const int bt = btype[p*BB + b];
    const float* cb = coords + (p*NATOM + b*AA)*3;

    // ---------- phase A: polar-site data (8 threads) + msep ballots (warps 5-7) ----------
    if (tid < NPOLB) {
        const int k = tid;
        const float wdist = wgp[0], wang = wgp[1];
        F3 w0v, w1v;
        int pol; bool valid;

        if (k < MD) {
            int hv = donHvy[bt*MD + k];
            int hh = donH  [bt*MD + k];
            valid = (k < n_donH[bt]);
            pol = hv;
            F3 Pv = ld3(cb + hv*3);
            F3 Hh = ld3(cb + hh*3);
            F3 dv = sub3(Hh, Pv);
            float s = wdist * rsqrtf(dot3(dv,dv) + 1e-12f);
            w0v.x = Pv.x + s*dv.x; w0v.y = Pv.y + s*dv.y; w0v.z = Pv.z + s*dv.z;
            w1v.x = 1e4f; w1v.y = 1e4f; w1v.z = 1e4f;   // donor water1 invalid sentinel
        } else {
            int m = k - MD;
            int a = accI[bt*MA + m];
            valid = (m < n_acc[bt]);
            pol = a;
            int rr    = ranges[(bt*AA + a)*2];
            int base  = bonds [(bt*AA + rr)*2 + 1];
            int rr2   = ranges[(bt*AA + base)*2];
            int base2 = bonds [(bt*AA + rr2)*2 + 1];
            F3 c  = ld3(cb + a*3);
            F3 bz = ld3(cb + base*3);
            F3 az = ld3(cb + base2*3);
            F3 e1 = norm3(sub3(c, bz));
            F3 nv = norm3(cross3(sub3(bz, az), e1));
            F3 e2 = cross3(nv, e1);
            int hy = hyb[bt*MA + m];
            const float* tors = (hy == 0) ? sp2t : ((hy == 1) ? sp3t : ringt);
            float ct = cosf(wang), st = sinf(wang);
            float c1 = -wdist * ct;
            float t0 = tors[0], t1 = tors[1];
            float c2a = wdist * st * cosf(t0), c3a = wdist * st * sinf(t0);
            float c2b = wdist * st * cosf(t1), c3b = wdist * st * sinf(t1);
            w0v.x = c.x + c1*e1.x + c2a*e2.x + c3a*nv.x;
            w0v.y = c.y + c1*e1.y + c2a*e2.y + c3a*nv.y;
            w0v.z = c.z + c1*e1.z + c2a*e2.z + c3a*nv.z;
            w1v.x = c.x + c1*e1.x + c2b*e2.x + c3b*nv.x;
            w1v.y = c.y + c1*e1.y + c2b*e2.y + c3b*nv.y;
            w1v.z = c.z + c1*e1.z + c2b*e2.z + c3b*nv.z;
        }

        const float* pr = lkp + (bt*AA + pol)*4;
        float ri = pr[0], dgi = pr[1], lami = pr[2];

        if (valid) {
            const float* xc = cb + pol*3;
            sSite[k][0] = xc[0]; sSite[k][1] = xc[1]; sSite[k][2] = xc[2];
        } else {
            sSite[k][0] = 1e9f; sSite[k][1] = 1e9f; sSite[k][2] = 1e9f;  // never in cutoff
        }
        sSite[k][3] = C_LK * dgi / lami;
        sSite[k][4] = 1.0f / lami;
        sSite[k][5] = ri;
        sSite[k][6] = w0v.x; sSite[k][7]  = w0v.y; sSite[k][8]  = w0v.z;
        sSite[k][9] = w1v.x; sSite[k][10] = w1v.y; sSite[k][11] = w1v.z;
        sPol[k] = pol;
    }

    if (tid >= 160) {   // warps 5,6,7: inter-block sep mask via ballot
        int lane = tid & 31;
        int w = (tid >> 5) - 5;
        int v = msep[(p*BB + b)*BB + w*32 + lane];
        unsigned m = __ballot_sync(0xFFFFFFFFu, v >= 4);
        if (lane == 0) sBp[w] = m;
    }
    __syncthreads();

    // ---------- phase B: intra path-distance masks (warp w -> site w) ----------
    {
        int w = tid >> 5, lane = tid & 31;
        int pol = sPol[w];
        int v = pd[(bt*AA + pol)*AA + lane];
        unsigned m = __ballot_sync(0xFFFFFFFFu, v >= 4);
        if (lane == 0) sIm[w] = m;
    }
    __syncthreads();

    if (tid < AA) {     // transpose to per-aj 8-bit site masks
        unsigned byte = 0;
        #pragma unroll
        for (int i = 0; i < NPOLB; i++) byte |= ((sIm[i] >> tid) & 1u) << i;
        sSame[tid] = (unsigned char)byte;
    }
    __syncthreads();

    // ---------- phase C: main pairwise loop ----------
    float xpx[NPOLB], xpy[NPOLB], xpz[NPOLB];
    #pragma unroll
    for (int i = 0; i < NPOLB; i++) {
        xpx[i] = sSite[i][0]; xpy[i] = sSite[i][1]; xpz[i] = sSite[i][2];
    }
    const unsigned bp0 = sBp[0], bp1 = sBp[1], bp2 = sBp[2];

    const float cutoff = lkg[0];
    const float cut2   = cutoff * cutoff;
    const float ramp2  = lkg[1];
    const float c0     = lkg[2] + ramp2;   // d2_low + ramp2
    const float invr   = 1.0f / ramp2;

    float s0 = 0.0f, s1 = 0.0f;
    const int j0 = blockIdx.y * CHUNK;
    const int pbase = p * NATOM;

    #pragma unroll
    for (int u = 0; u < CHUNK/256; u++) {
        int j  = j0 + u*256 + tid;
        int bj = j >> 5;
        int aj = j & 31;
        const float* cp = coords + (pbase + j)*3;
        float cx = __ldg(cp), cy = __ldg(cp+1), cz = __ldg(cp+2);
        int btj = __ldg(&btype[p*BB + bj]);
        int idx = btj*AA + aj;
        float vj = __ldg(&isH[idx]) ? 0.0f : __ldg(&lkp[idx*4 + 3]);
        unsigned inter =
            ((bj < 32) ? (bp0 >> bj) : (bj < 64) ? (bp1 >> (bj-32)) : (bp2 >> (bj-64))) & 1u;
        unsigned m8 = (bj == b) ? (unsigned)sSame[aj] : (inter ? 0xFFu : 0u);

        if (vj > 0.0f && m8) {
            float rj = __ldg(&lkp[idx*4]);
            #pragma unroll
            for (int i = 0; i < NPOLB; i++) {
                float dx = xpx[i] - cx;
                float dy = xpy[i] - cy;
                float dz = xpz[i] - cz;
                float d2 = fmaf(dx, dx, fmaf(dy, dy, dz*dz));
                if (((m8 >> i) & 1u) && d2 < cut2) {
                    d2 = fmaxf(d2, 0.01f);
                    float d  = sqrtf(d2);
                    float Ki = sSite[i][3];
                    float il = sSite[i][4];
                    float ri = sSite[i][5];
                    float x  = (d - ri - rj) * il;
                    float lk = __fdividef(Ki * vj * __expf(-x*x), d2);
                    float ax = sSite[i][6] - cx, ay = sSite[i][7]  - cy, az = sSite[i][8]  - cz;
                    float d2a = fmaf(ax, ax, fmaf(ay, ay, az*az));
                    float bx = sSite[i][9] - cx, by = sSite[i][10] - cy, bz = sSite[i][11] - cz;
                    float d2b = fmaf(bx, bx, fmaf(by, by, bz*bz));
                    float dm = fminf(d2a, d2b);
                    float wt = __saturatef((c0 - dm) * invr);
                    float frac = wt * wt * (3.0f - 2.0f*wt);
                    s0 += lk;
                    s1 += lk * frac;
                }
            }
        }
    }

    // ---------- reduction + self-resetting global accumulation ----------
    #pragma unroll
    for (int off = 16; off > 0; off >>= 1) {
        s0 += __shfl_xor_sync(0xFFFFFFFFu, s0, off);
        s1 += __shfl_xor_sync(0xFFFFFFFFu, s1, off);
    }
    int wid  = tid >> 5;
    int lane = tid & 31;
    if (lane == 0) { sred[0][wid] = s0; sred[1][wid] = s1; }
    __syncthreads();
    if (tid == 0) {
        float t0 = 0.f, t1 = 0.f;
        #pragma unroll
        for (int w = 0; w < 8; w++) { t0 += sred[0][w]; t1 += sred[1][w]; }
        atomicAdd(&g_acc[p],     t0);
        atomicAdd(&g_acc[2 + p], t1);
        __threadfence();
        unsigned done = atomicAdd(&g_cnt, 1u);
        if (done == NBLK - 1) {
            // last CTA: drain + reset accumulators, write output (2, P) row-major
            out[0] = atomicExch(&g_acc[0], 0.0f);
            out[1] = atomicExch(&g_acc[1], 0.0f);
            out[2] = atomicExch(&g_acc[2], 0.0f);
            out[3] = atomicExch(&g_acc[3], 0.0f);
            atomicExch(&g_cnt, 0u);
        }
    }
}

extern "C" void kernel_launch(void* const* d_in, const int* in_sizes, int n_in,
                              void* d_out, int out_size)
{
    const float* coords = (const float*)d_in[0];
    const int*   btype  = (const int*)  d_in[1];
    const int*   msep   = (const int*)  d_in[2];
    /* d_in[3] = bt_n_atoms (unused, always A) */
    const int*   bonds  = (const int*)  d_in[4];
    const int*   ranges = (const int*)  d_in[5];
    const int*   ndonH  = (const int*)  d_in[6];
    const int*   nacc   = (const int*)  d_in[7];
    const int*   donH   = (const int*)  d_in[8];
    const int*   donHvy = (const int*)  d_in[9];
    const int*   accI   = (const int*)  d_in[10];
    const int*   hyb    = (const int*)  d_in[11];
    const int*   isH    = (const int*)  d_in[12];
    const float* lkp    = (const float*)d_in[13];
    const int*   pd     = (const int*)  d_in[14];
    const float* lkg    = (const float*)d_in[15];
    const float* wgp    = (const float*)d_in[16];
    const float* sp2t   = (const float*)d_in[17];
    const float* sp3t   = (const float*)d_in[18];
    const float* ringt  = (const float*)d_in[19];
    float* out = (float*)d_out;

    dim3 grid(PP*BB, JSPLIT);
    lkball_fused_kernel<<<grid, 256>>>(coords, btype, msep, bonds, ranges,
                                       ndonH, nacc, donH, donHvy, accI, hyb, isH,
                                       lkp, pd, lkg, wgp, sp2t, sp3t, ringt, out);
}